// round 12
// baseline (speedup 1.0000x reference)
#include <cuda_runtime.h>
#include <math.h>

#define Kn 20000
#define In 50000
#define Dn 128
#define Nn (Kn + In)
#define E1n 320000
#define E2n 640000
#define ETOT (E1n + 2 * E2n)
#define SEGS 90000              // 20000 dir + 20000 ke + 50000 ek
#define SCAN_BLKS 352           // ceil(90000/256)
#define SCAL_BLKS ((Nn * 32 + 255) / 256)      // 8750
#define CNT_BLKS  ((ETOT / 4 + 255) / 256)     // 1563
#define ZERO_BLKS ((SEGS + 127) / 128)         // 704

// ---------------- device scratch (static, allocation-free) ----------------
__device__ __align__(16) float g_ssrc_dir[Kn], g_sdst_dir[Kn];
__device__ __align__(16) float g_ssrc_ke[Nn],  g_sdst_ke[Nn];
__device__ __align__(16) float g_ssrc_ek[Nn],  g_sdst_ek[Nn];
__device__ __align__(16) float g_agg_dir[Kn * Dn];
__device__ __align__(16) float g_agg_ke[Kn * Dn];
__device__ __align__(16) float g_agg_ek[(size_t)In * Dn];
__device__ __align__(16) float g_A[Kn * Dn], g_B[Kn * Dn];
__device__ __align__(16) float g_s1[Kn], g_s2[Kn];
__device__ __align__(16) float g_pq[6 * Dn];
// CSR machinery
__device__ __align__(16) int   g_cnt[SEGS];
__device__ __align__(16) int   g_off[SEGS];
__device__ __align__(16) int   g_pos[SEGS];
__device__ __align__(16) int   g_bsum[SCAN_BLKS];
__device__ __align__(16) int   g_bbase[512];
__device__ __align__(16) int2  g_csr[ETOT];      // {unified src id, __float_as_int(ex)}

// ---------------- helpers ----------------
typedef unsigned long long u64;

__device__ __forceinline__ float warp_sum(float v) {
    #pragma unroll
    for (int o = 16; o; o >>= 1) v += __shfl_xor_sync(0xffffffffu, v, o);
    return v;
}
__device__ __forceinline__ float lrelu(float x) { return x > 0.0f ? x : 0.01f * x; }

__device__ __forceinline__ u64 pack2(float lo, float hi) {
    u64 r; asm("mov.b64 %0, {%1,%2};" : "=l"(r) : "f"(lo), "f"(hi)); return r;
}
__device__ __forceinline__ u64 ffma2(u64 a, u64 b, u64 c) {
    u64 d; asm("fma.rn.f32x2 %0, %1, %2, %3;" : "=l"(d) : "l"(a), "l"(b), "l"(c)); return d;
}
__device__ __forceinline__ float hsum2(u64 v) {
    float2 f; asm("mov.b64 {%0,%1}, %2;" : "=f"(f.x), "=f"(f.y) : "l"(v));
    return f.x + f.y;
}

// ---------------- prep (pq mat-vecs) + zero counts, one kernel --------------
// blocks 0..5: p = W @ a[:D], q = W @ a[D:]; blocks 6..: zero g_cnt
__global__ void k_prep0(const float* __restrict__ Wd,  const float* __restrict__ ad,
                        const float* __restrict__ Wke, const float* __restrict__ ake,
                        const float* __restrict__ Wek, const float* __restrict__ aek) {
    int blk = blockIdx.x;
    if (blk >= 6) {
        int i = (blk - 6) * 128 + threadIdx.x;
        if (i < SEGS) g_cnt[i] = 0;
        return;
    }
    int g = blk >> 1, h = blk & 1;
    const float* W = (g == 0) ? Wd : (g == 1) ? Wke : Wek;
    const float* a = ((g == 0) ? ad : (g == 1) ? ake : aek) + h * Dn;
    __shared__ float sa[Dn];
    sa[threadIdx.x] = a[threadIdx.x];
    __syncthreads();
    const float* wr = W + threadIdx.x * Dn;
    float s = 0.f;
    #pragma unroll 8
    for (int j = 0; j < Dn; j++) s += wr[j] * sa[j];
    g_pq[blk * Dn + threadIdx.x] = s;
}

// ---------------- per-node scalars + segment count, one kernel --------------
// blocks [0, SCAL_BLKS): warp-per-node scalars for all 3 GATs
// blocks [SCAL_BLKS, +CNT_BLKS): int4 histogram of kept dsts
__global__ void k_scal_count(const float4* __restrict__ exer, const float4* __restrict__ kn,
                             const int4* __restrict__ d0, const int4* __restrict__ d1,
                             const int4* __restrict__ d2) {
    if (blockIdx.x >= SCAL_BLKS) {
        int q = (blockIdx.x - SCAL_BLKS) * blockDim.x + threadIdx.x;
        const int Q1 = E1n / 4, Q2 = (E1n + E2n) / 4, QT = ETOT / 4;
        if (q >= QT) return;
        if (q < Q1) {
            int4 v = __ldg(d0 + q);                   // dir dst always in [0,Kn)
            atomicAdd(&g_cnt[v.x], 1); atomicAdd(&g_cnt[v.y], 1);
            atomicAdd(&g_cnt[v.z], 1); atomicAdd(&g_cnt[v.w], 1);
        } else if (q < Q2) {
            int4 v = __ldg(d1 + (q - Q1));
            if (v.x >= In) atomicAdd(&g_cnt[Kn + (v.x - In)], 1);
            if (v.y >= In) atomicAdd(&g_cnt[Kn + (v.y - In)], 1);
            if (v.z >= In) atomicAdd(&g_cnt[Kn + (v.z - In)], 1);
            if (v.w >= In) atomicAdd(&g_cnt[Kn + (v.w - In)], 1);
        } else {
            int4 v = __ldg(d2 + (q - Q2));
            if (v.x < In) atomicAdd(&g_cnt[2 * Kn + v.x], 1);
            if (v.y < In) atomicAdd(&g_cnt[2 * Kn + v.y], 1);
            if (v.z < In) atomicAdd(&g_cnt[2 * Kn + v.z], 1);
            if (v.w < In) atomicAdd(&g_cnt[2 * Kn + v.w], 1);
        }
        return;
    }
    int w = (blockIdx.x * blockDim.x + threadIdx.x) >> 5;
    int lane = threadIdx.x & 31;
    if (w >= Nn) return;
    bool iskn = (w >= In);
    const float4* h = iskn ? kn + (size_t)(w - In) * 32 : exer + (size_t)w * 32;
    float4 v = __ldg(h + lane);
    const float4* pq = (const float4*)g_pq;
    float4 a = pq[2 * 32 + lane], b = pq[3 * 32 + lane];
    float4 c = pq[4 * 32 + lane], d = pq[5 * 32 + lane];
    float s0 = v.x * a.x + v.y * a.y + v.z * a.z + v.w * a.w;
    float s1 = v.x * b.x + v.y * b.y + v.z * b.z + v.w * b.w;
    float s2 = v.x * c.x + v.y * c.y + v.z * c.z + v.w * c.w;
    float s3 = v.x * d.x + v.y * d.y + v.z * d.z + v.w * d.w;
    s0 = warp_sum(s0); s1 = warp_sum(s1); s2 = warp_sum(s2); s3 = warp_sum(s3);
    if (lane == 0) {
        g_ssrc_ke[w] = s0; g_sdst_ke[w] = s1;
        g_ssrc_ek[w] = s2; g_sdst_ek[w] = s3;
    }
    if (iskn) {
        float4 p = pq[0 * 32 + lane], q = pq[1 * 32 + lane];
        float sp = v.x * p.x + v.y * p.y + v.z * p.z + v.w * p.w;
        float sq = v.x * q.x + v.y * q.y + v.z * q.z + v.w * q.w;
        sp = warp_sum(sp); sq = warp_sum(sq);
        if (lane == 0) { g_ssrc_dir[w - In] = sp; g_sdst_dir[w - In] = sq; }
    }
}

// ---------------- scans ----------------
__global__ void k_scanA() {
    __shared__ int sm[256];
    int t = threadIdx.x;
    int i = blockIdx.x * 256 + t;
    int v = (i < SEGS) ? g_cnt[i] : 0;
    sm[t] = v;
    __syncthreads();
    #pragma unroll
    for (int o = 128; o; o >>= 1) {
        if (t < o) sm[t] += sm[t + o];
        __syncthreads();
    }
    if (t == 0) g_bsum[blockIdx.x] = sm[0];
}

__global__ void k_scanB() {
    __shared__ int sa[512], sb[512];
    int t = threadIdx.x;
    int v = (t < SCAN_BLKS) ? g_bsum[t] : 0;
    sa[t] = v;
    __syncthreads();
    int* pin = sa; int* pout = sb;
    #pragma unroll
    for (int o = 1; o < 512; o <<= 1) {
        pout[t] = pin[t] + ((t >= o) ? pin[t - o] : 0);
        __syncthreads();
        int* tmp = pin; pin = pout; pout = tmp;
    }
    g_bbase[t] = pin[t] - v;   // exclusive
}

__global__ void k_scanC() {
    __shared__ int sa[256], sb[256];
    int t = threadIdx.x;
    int i = blockIdx.x * 256 + t;
    int v = (i < SEGS) ? g_cnt[i] : 0;
    sa[t] = v;
    __syncthreads();
    int* pin = sa; int* pout = sb;
    #pragma unroll
    for (int o = 1; o < 256; o <<= 1) {
        pout[t] = pin[t] + ((t >= o) ? pin[t - o] : 0);
        __syncthreads();
        int* tmp = pin; pin = pout; pout = tmp;
    }
    if (i < SEGS) {
        int off = g_bbase[blockIdx.x] + pin[t] - v;
        g_off[i] = off;
        g_pos[i] = off;
    }
}

// ---------------- scatter: int4-vectorized, 4 edges per thread --------------
template <int G>
__device__ __forceinline__ void scatter_elem(int s, int d) {
    const int lo   = (G == 1) ? In : 0;
    const int hi   = (G == 0) ? Kn : (G == 1) ? Nn : In;
    const int base = (G == 0) ? 0 : (G == 1) ? Kn : 2 * Kn;
    if (d < lo || d >= hi) return;
    const float* ss = (G == 0) ? g_ssrc_dir : (G == 1) ? g_ssrc_ke : g_ssrc_ek;
    const float* sd = (G == 0) ? g_sdst_dir : (G == 1) ? g_sdst_ke : g_sdst_ek;
    float ev = expf(lrelu(__ldg(ss + s) + __ldg(sd + d)));
    int pos = atomicAdd(&g_pos[base + (d - lo)], 1);
    int u = (G == 0) ? s + In : s;                 // unified node id
    g_csr[pos] = make_int2(u, __float_as_int(ev));
}

template <int G>
__device__ __forceinline__ void scatter_quad(int q, const int4* __restrict__ src,
                                             const int4* __restrict__ dst) {
    int4 d = __ldg(dst + q);
    int4 s = __ldg(src + q);
    scatter_elem<G>(s.x, d.x);
    scatter_elem<G>(s.y, d.y);
    scatter_elem<G>(s.z, d.z);
    scatter_elem<G>(s.w, d.w);
}

__global__ void k_scatter(const int4* __restrict__ s0, const int4* __restrict__ d0,
                          const int4* __restrict__ s1, const int4* __restrict__ d1,
                          const int4* __restrict__ s2, const int4* __restrict__ d2) {
    int q = blockIdx.x * blockDim.x + threadIdx.x;
    const int Q1 = E1n / 4, Q2 = (E1n + E2n) / 4, QT = ETOT / 4;
    if (q >= QT) return;
    if (q < Q1)      scatter_quad<0>(q, s0, d0);
    else if (q < Q2) scatter_quad<1>(q - Q1, s1, d1);
    else             scatter_quad<2>(q - Q2, s2, d2);
}

// ---------------- single-pass softmax + aggregation: warp per segment --------
__global__ void __launch_bounds__(256) k_seg(const float4* __restrict__ exer,
                                             const float4* __restrict__ kn) {
    int w = (blockIdx.x * blockDim.x + threadIdx.x) >> 5;
    if (w >= SEGS) return;
    int lane = threadIdx.x & 31;
    int start = g_off[w];
    int end   = start + g_cnt[w];

    float4 acc = make_float4(0.f, 0.f, 0.f, 0.f);
    float den = 0.f;
    int e = start;
    for (; e + 4 <= end; e += 4) {
        int2 c0 = __ldg(g_csr + e);
        int2 c1 = __ldg(g_csr + e + 1);
        int2 c2 = __ldg(g_csr + e + 2);
        int2 c3 = __ldg(g_csr + e + 3);
        const float4* p0 = (c0.x < In) ? exer + (size_t)c0.x * 32 : kn + (size_t)(c0.x - In) * 32;
        const float4* p1 = (c1.x < In) ? exer + (size_t)c1.x * 32 : kn + (size_t)(c1.x - In) * 32;
        const float4* p2 = (c2.x < In) ? exer + (size_t)c2.x * 32 : kn + (size_t)(c2.x - In) * 32;
        const float4* p3 = (c3.x < In) ? exer + (size_t)c3.x * 32 : kn + (size_t)(c3.x - In) * 32;
        float4 v0 = __ldg(p0 + lane);
        float4 v1 = __ldg(p1 + lane);
        float4 v2 = __ldg(p2 + lane);
        float4 v3 = __ldg(p3 + lane);
        float e0 = __int_as_float(c0.y), e1 = __int_as_float(c1.y);
        float e2f = __int_as_float(c2.y), e3 = __int_as_float(c3.y);
        den += (e0 + e1) + (e2f + e3);
        acc.x = fmaf(e0, v0.x, acc.x); acc.y = fmaf(e0, v0.y, acc.y);
        acc.z = fmaf(e0, v0.z, acc.z); acc.w = fmaf(e0, v0.w, acc.w);
        acc.x = fmaf(e1, v1.x, acc.x); acc.y = fmaf(e1, v1.y, acc.y);
        acc.z = fmaf(e1, v1.z, acc.z); acc.w = fmaf(e1, v1.w, acc.w);
        acc.x = fmaf(e2f, v2.x, acc.x); acc.y = fmaf(e2f, v2.y, acc.y);
        acc.z = fmaf(e2f, v2.z, acc.z); acc.w = fmaf(e2f, v2.w, acc.w);
        acc.x = fmaf(e3, v3.x, acc.x); acc.y = fmaf(e3, v3.y, acc.y);
        acc.z = fmaf(e3, v3.z, acc.z); acc.w = fmaf(e3, v3.w, acc.w);
    }
    for (; e < end; e++) {
        int2 c0 = __ldg(g_csr + e);
        const float4* p0 = (c0.x < In) ? exer + (size_t)c0.x * 32 : kn + (size_t)(c0.x - In) * 32;
        float4 v0 = __ldg(p0 + lane);
        float e0 = __int_as_float(c0.y);
        den += e0;
        acc.x = fmaf(e0, v0.x, acc.x); acc.y = fmaf(e0, v0.y, acc.y);
        acc.z = fmaf(e0, v0.z, acc.z); acc.w = fmaf(e0, v0.w, acc.w);
    }
    float inv = (den > 0.f) ? 1.0f / den : 0.f;
    acc.x *= inv; acc.y *= inv; acc.z *= inv; acc.w *= inv;

    float* orow;
    if (w < Kn)            orow = g_agg_dir + (size_t)w * Dn;
    else if (w < 2 * Kn)   orow = g_agg_ke  + (size_t)(w - Kn) * Dn;
    else                   orow = g_agg_ek  + (size_t)(w - 2 * Kn) * Dn;
    ((float4*)orow)[lane] = acc;
}

// ---------------- fused row GEMM (+ rel head for A/B) via fma.rn.f32x2 --------
#define GEMM_BLKS_K ((Kn + 31) / 32)   // 625
#define GEMM_BLKS_I ((In + 31) / 32)   // 1563
#define GEMM_BLKS_TOT (2 * GEMM_BLKS_K + GEMM_BLKS_I)

__global__ void __launch_bounds__(128) k_gemm(const float* __restrict__ Wd,
                                              const float* __restrict__ Wke,
                                              const float* __restrict__ Wek,
                                              const float* __restrict__ relW1,
                                              const float* __restrict__ relb1,
                                              const float* __restrict__ relw2,
                                              float* __restrict__ exer_out) {
    int blk = blockIdx.x;
    const float* agg; const float* W; float* of; int rows; int row0;
    bool do_rel = (blk < 2 * GEMM_BLKS_K);
    if (blk < GEMM_BLKS_K) {
        agg = g_agg_dir; W = Wd;  of = g_A;      rows = Kn; row0 = blk * 32;
    } else if (blk < 2 * GEMM_BLKS_K) {
        agg = g_agg_ke;  W = Wke; of = g_B;      rows = Kn; row0 = (blk - GEMM_BLKS_K) * 32;
    } else {
        agg = g_agg_ek;  W = Wek; of = exer_out; rows = In; row0 = (blk - 2 * GEMM_BLKS_K) * 32;
    }
    __shared__ __align__(16) float shA[32][Dn];
    int t = threadIdx.x;
    const float4* agg4 = (const float4*)agg;
    for (int i = t; i < 1024; i += 128) {
        int r = i >> 5, c4 = i & 31;
        float4 v = (row0 + r < rows) ? __ldg(agg4 + (size_t)(row0 + r) * 32 + c4)
                                     : make_float4(0.f, 0.f, 0.f, 0.f);
        *(float4*)&shA[r][c4 * 4] = v;
    }
    __syncthreads();
    int cg = t & 31, rs = t >> 5;
    const float4* W4 = (const float4*)W;
    u64 acc2[8][4];
    #pragma unroll
    for (int r = 0; r < 8; r++)
        #pragma unroll
        for (int c = 0; c < 4; c++) acc2[r][c] = 0ull;
    #pragma unroll 4
    for (int k = 0; k < Dn; k += 2) {
        float4 wa = __ldg(W4 + k * 32 + cg);
        float4 wb = __ldg(W4 + (k + 1) * 32 + cg);
        u64 wx = pack2(wa.x, wb.x), wy = pack2(wa.y, wb.y);
        u64 wz = pack2(wa.z, wb.z), ww = pack2(wa.w, wb.w);
        #pragma unroll
        for (int r = 0; r < 8; r++) {
            u64 a2 = *(const u64*)&shA[rs * 8 + r][k];
            acc2[r][0] = ffma2(a2, wx, acc2[r][0]);
            acc2[r][1] = ffma2(a2, wy, acc2[r][1]);
            acc2[r][2] = ffma2(a2, wz, acc2[r][2]);
            acc2[r][3] = ffma2(a2, ww, acc2[r][3]);
        }
    }
    // finalize output tile
    float4 outv[8];
    #pragma unroll
    for (int r = 0; r < 8; r++)
        outv[r] = make_float4(hsum2(acc2[r][0]), hsum2(acc2[r][1]),
                              hsum2(acc2[r][2]), hsum2(acc2[r][3]));
    float4* out4 = (float4*)of;
    #pragma unroll
    for (int r = 0; r < 8; r++) {
        int row = row0 + rs * 8 + r;
        if (row < rows) out4[(size_t)row * 32 + cg] = outv[r];
    }
    if (!do_rel) return;

    // ---- fused rel head: s[row] = sum_c tanh((OUT @ relW1)[row][c] + b1[c]) * w2[c]
    __syncthreads();                       // everyone done reading old shA
    #pragma unroll
    for (int r = 0; r < 8; r++)
        *(float4*)&shA[rs * 8 + r][cg * 4] = outv[r];
    __syncthreads();

    const float4* R4 = (const float4*)relW1;
    #pragma unroll
    for (int r = 0; r < 8; r++)
        #pragma unroll
        for (int c = 0; c < 4; c++) acc2[r][c] = 0ull;
    #pragma unroll 4
    for (int k = 0; k < Dn; k += 2) {
        float4 wa = __ldg(R4 + k * 32 + cg);
        float4 wb = __ldg(R4 + (k + 1) * 32 + cg);
        u64 wx = pack2(wa.x, wb.x), wy = pack2(wa.y, wb.y);
        u64 wz = pack2(wa.z, wb.z), ww = pack2(wa.w, wb.w);
        #pragma unroll
        for (int r = 0; r < 8; r++) {
            u64 a2 = *(const u64*)&shA[rs * 8 + r][k];
            acc2[r][0] = ffma2(a2, wx, acc2[r][0]);
            acc2[r][1] = ffma2(a2, wy, acc2[r][1]);
            acc2[r][2] = ffma2(a2, wz, acc2[r][2]);
            acc2[r][3] = ffma2(a2, ww, acc2[r][3]);
        }
    }
    float4 bb = __ldg(((const float4*)relb1) + cg);
    float4 ww2 = __ldg(((const float4*)relw2) + cg);
    float part[8];
    #pragma unroll
    for (int r = 0; r < 8; r++) {
        part[r] = tanhf(hsum2(acc2[r][0]) + bb.x) * ww2.x
                + tanhf(hsum2(acc2[r][1]) + bb.y) * ww2.y
                + tanhf(hsum2(acc2[r][2]) + bb.z) * ww2.z
                + tanhf(hsum2(acc2[r][3]) + bb.w) * ww2.w;
    }
    #pragma unroll
    for (int o = 16; o; o >>= 1) {
        #pragma unroll
        for (int r = 0; r < 8; r++)
            part[r] += __shfl_xor_sync(0xffffffffu, part[r], o);
    }
    if (cg == 0) {
        float* sout = (blk < GEMM_BLKS_K) ? g_s1 : g_s2;
        #pragma unroll
        for (int r = 0; r < 8; r++) {
            int row = row0 + rs * 8 + r;
            if (row < Kn) sout[row] = part[r];
        }
    }
}

// kn_out = softmax([s1,s2]) gated mix of A and B
__global__ void k_combine(float4* __restrict__ out) {
    int i = blockIdx.x * blockDim.x + threadIdx.x;
    if (i >= Kn * 32) return;
    int row = i >> 5;
    float s1 = g_s1[row], s2 = g_s2[row];
    float mx = fmaxf(s1, s2);
    float e1 = expf(s1 - mx), e2 = expf(s2 - mx);
    float inv = 1.0f / (e1 + e2);
    float w1 = e1 * inv, w2 = e2 * inv;
    float4 a = ((const float4*)g_A)[i];
    float4 b = ((const float4*)g_B)[i];
    out[i] = make_float4(w1 * a.x + w2 * b.x, w1 * a.y + w2 * b.y,
                         w1 * a.z + w2 * b.z, w1 * a.w + w2 * b.w);
}

// ---------------- launch ----------------
extern "C" void kernel_launch(void* const* d_in, const int* in_sizes, int n_in,
                              void* d_out, int out_size) {
    (void)in_sizes; (void)n_in; (void)out_size;
    const float* kn    = (const float*)d_in[0];
    const float* exer  = (const float*)d_in[1];
    const float* Wd    = (const float*)d_in[2];
    const float* ad    = (const float*)d_in[3];
    const float* Wke   = (const float*)d_in[4];
    const float* ake   = (const float*)d_in[5];
    const float* Wek   = (const float*)d_in[6];
    const float* aek   = (const float*)d_in[7];
    const float* relW1 = (const float*)d_in[8];
    const float* relb1 = (const float*)d_in[9];
    const float* relw2 = (const float*)d_in[10];
    const int* dsrc  = (const int*)d_in[11];
    const int* ddst  = (const int*)d_in[12];
    const int* kesrc = (const int*)d_in[13];
    const int* kedst = (const int*)d_in[14];
    const int* eksrc = (const int*)d_in[15];
    const int* ekdst = (const int*)d_in[16];
    float* out = (float*)d_out;

    const float4* kn4   = (const float4*)kn;
    const float4* exer4 = (const float4*)exer;

    k_prep0<<<6 + ZERO_BLKS, 128>>>(Wd, ad, Wke, ake, Wek, aek);
    k_scal_count<<<SCAL_BLKS + CNT_BLKS, 256>>>(exer4, kn4,
                                                (const int4*)ddst, (const int4*)kedst,
                                                (const int4*)ekdst);
    k_scanA<<<SCAN_BLKS, 256>>>();
    k_scanB<<<1, 512>>>();
    k_scanC<<<SCAN_BLKS, 256>>>();
    k_scatter<<<(ETOT / 4 + 255) / 256, 256>>>((const int4*)dsrc, (const int4*)ddst,
                                               (const int4*)kesrc, (const int4*)kedst,
                                               (const int4*)eksrc, (const int4*)ekdst);
    k_seg<<<(SEGS * 32 + 255) / 256, 256>>>(exer4, kn4);
    k_gemm<<<GEMM_BLKS_TOT, 128>>>(Wd, Wke, Wek, relW1, relb1, relw2,
                                   out + (size_t)Kn * Dn);
    k_combine<<<(Kn * 32 + 255) / 256, 256>>>((float4*)out);
}

// round 13
// speedup vs baseline: 1.0097x; 1.0097x over previous
#include <cuda_runtime.h>
#include <math.h>

#define Kn 20000
#define In 50000
#define Dn 128
#define Nn (Kn + In)
#define E1n 320000
#define E2n 640000
#define ETOT (E1n + 2 * E2n)
#define SEGS 90000              // 20000 dir + 20000 ke + 50000 ek
#define SCAN_BLKS 352           // ceil(90000/256)
#define SCAL_BLKS ((Nn * 32 + 255) / 256)      // 8750
#define CNT_BLKS  ((ETOT / 4 + 255) / 256)     // 1563
#define ZERO_BLKS ((SEGS + 127) / 128)         // 704

// ---------------- device scratch (static, allocation-free) ----------------
__device__ __align__(16) float g_ssrc_dir[Kn], g_sdst_dir[Kn];
__device__ __align__(16) float g_ssrc_ke[Nn],  g_sdst_ke[Nn];
__device__ __align__(16) float g_ssrc_ek[Nn],  g_sdst_ek[Nn];
__device__ __align__(16) float g_agg_dir[Kn * Dn];
__device__ __align__(16) float g_agg_ke[Kn * Dn];
__device__ __align__(16) float g_agg_ek[(size_t)In * Dn];
__device__ __align__(16) float g_A[Kn * Dn], g_B[Kn * Dn];
__device__ __align__(16) float g_s1[Kn], g_s2[Kn];
__device__ __align__(16) float g_pq[6 * Dn];
// CSR machinery
__device__ __align__(16) int   g_cnt[SEGS];
__device__ __align__(16) int   g_off[SEGS];
__device__ __align__(16) int   g_pos[SEGS];
__device__ __align__(16) int   g_bsum[SCAN_BLKS];
__device__ __align__(16) int   g_bbase[512];
__device__ __align__(16) int2  g_csr[ETOT];      // {unified src id, __float_as_int(ex)}

// ---------------- helpers ----------------
typedef unsigned long long u64;

__device__ __forceinline__ float warp_sum(float v) {
    #pragma unroll
    for (int o = 16; o; o >>= 1) v += __shfl_xor_sync(0xffffffffu, v, o);
    return v;
}
__device__ __forceinline__ float lrelu(float x) { return x > 0.0f ? x : 0.01f * x; }

__device__ __forceinline__ u64 pack2(float lo, float hi) {
    u64 r; asm("mov.b64 %0, {%1,%2};" : "=l"(r) : "f"(lo), "f"(hi)); return r;
}
__device__ __forceinline__ u64 ffma2(u64 a, u64 b, u64 c) {
    u64 d; asm("fma.rn.f32x2 %0, %1, %2, %3;" : "=l"(d) : "l"(a), "l"(b), "l"(c)); return d;
}
__device__ __forceinline__ float hsum2(u64 v) {
    float2 f; asm("mov.b64 {%0,%1}, %2;" : "=f"(f.x), "=f"(f.y) : "l"(v));
    return f.x + f.y;
}

// ---------------- prep (pq mat-vecs) + zero counts, one kernel --------------
// blocks 0..5: p = W @ a[:D], q = W @ a[D:]; blocks 6..: zero g_cnt
__global__ void k_prep0(const float* __restrict__ Wd,  const float* __restrict__ ad,
                        const float* __restrict__ Wke, const float* __restrict__ ake,
                        const float* __restrict__ Wek, const float* __restrict__ aek) {
    int blk = blockIdx.x;
    if (blk >= 6) {
        int i = (blk - 6) * 128 + threadIdx.x;
        if (i < SEGS) g_cnt[i] = 0;
        return;
    }
    int g = blk >> 1, h = blk & 1;
    const float* W = (g == 0) ? Wd : (g == 1) ? Wke : Wek;
    const float* a = ((g == 0) ? ad : (g == 1) ? ake : aek) + h * Dn;
    __shared__ float sa[Dn];
    sa[threadIdx.x] = a[threadIdx.x];
    __syncthreads();
    const float* wr = W + threadIdx.x * Dn;
    float s = 0.f;
    #pragma unroll 8
    for (int j = 0; j < Dn; j++) s += wr[j] * sa[j];
    g_pq[blk * Dn + threadIdx.x] = s;
}

// ---------------- per-node scalars + segment count, one kernel --------------
// blocks [0, SCAL_BLKS): warp-per-node scalars for all 3 GATs
// blocks [SCAL_BLKS, +CNT_BLKS): int4 histogram of kept dsts
__global__ void k_scal_count(const float4* __restrict__ exer, const float4* __restrict__ kn,
                             const int4* __restrict__ d0, const int4* __restrict__ d1,
                             const int4* __restrict__ d2) {
    if (blockIdx.x >= SCAL_BLKS) {
        int q = (blockIdx.x - SCAL_BLKS) * blockDim.x + threadIdx.x;
        const int Q1 = E1n / 4, Q2 = (E1n + E2n) / 4, QT = ETOT / 4;
        if (q >= QT) return;
        if (q < Q1) {
            int4 v = __ldg(d0 + q);                   // dir dst always in [0,Kn)
            atomicAdd(&g_cnt[v.x], 1); atomicAdd(&g_cnt[v.y], 1);
            atomicAdd(&g_cnt[v.z], 1); atomicAdd(&g_cnt[v.w], 1);
        } else if (q < Q2) {
            int4 v = __ldg(d1 + (q - Q1));
            if (v.x >= In) atomicAdd(&g_cnt[Kn + (v.x - In)], 1);
            if (v.y >= In) atomicAdd(&g_cnt[Kn + (v.y - In)], 1);
            if (v.z >= In) atomicAdd(&g_cnt[Kn + (v.z - In)], 1);
            if (v.w >= In) atomicAdd(&g_cnt[Kn + (v.w - In)], 1);
        } else {
            int4 v = __ldg(d2 + (q - Q2));
            if (v.x < In) atomicAdd(&g_cnt[2 * Kn + v.x], 1);
            if (v.y < In) atomicAdd(&g_cnt[2 * Kn + v.y], 1);
            if (v.z < In) atomicAdd(&g_cnt[2 * Kn + v.z], 1);
            if (v.w < In) atomicAdd(&g_cnt[2 * Kn + v.w], 1);
        }
        return;
    }
    int w = (blockIdx.x * blockDim.x + threadIdx.x) >> 5;
    int lane = threadIdx.x & 31;
    if (w >= Nn) return;
    bool iskn = (w >= In);
    const float4* h = iskn ? kn + (size_t)(w - In) * 32 : exer + (size_t)w * 32;
    float4 v = __ldg(h + lane);
    const float4* pq = (const float4*)g_pq;
    float4 a = pq[2 * 32 + lane], b = pq[3 * 32 + lane];
    float4 c = pq[4 * 32 + lane], d = pq[5 * 32 + lane];
    float s0 = v.x * a.x + v.y * a.y + v.z * a.z + v.w * a.w;
    float s1 = v.x * b.x + v.y * b.y + v.z * b.z + v.w * b.w;
    float s2 = v.x * c.x + v.y * c.y + v.z * c.z + v.w * c.w;
    float s3 = v.x * d.x + v.y * d.y + v.z * d.z + v.w * d.w;
    s0 = warp_sum(s0); s1 = warp_sum(s1); s2 = warp_sum(s2); s3 = warp_sum(s3);
    if (lane == 0) {
        g_ssrc_ke[w] = s0; g_sdst_ke[w] = s1;
        g_ssrc_ek[w] = s2; g_sdst_ek[w] = s3;
    }
    if (iskn) {
        float4 p = pq[0 * 32 + lane], q = pq[1 * 32 + lane];
        float sp = v.x * p.x + v.y * p.y + v.z * p.z + v.w * p.w;
        float sq = v.x * q.x + v.y * q.y + v.z * q.z + v.w * q.w;
        sp = warp_sum(sp); sq = warp_sum(sq);
        if (lane == 0) { g_ssrc_dir[w - In] = sp; g_sdst_dir[w - In] = sq; }
    }
}

// ---------------- scans ----------------
__global__ void k_scanA() {
    __shared__ int sm[256];
    int t = threadIdx.x;
    int i = blockIdx.x * 256 + t;
    int v = (i < SEGS) ? g_cnt[i] : 0;
    sm[t] = v;
    __syncthreads();
    #pragma unroll
    for (int o = 128; o; o >>= 1) {
        if (t < o) sm[t] += sm[t + o];
        __syncthreads();
    }
    if (t == 0) g_bsum[blockIdx.x] = sm[0];
}

__global__ void k_scanB() {
    __shared__ int sa[512], sb[512];
    int t = threadIdx.x;
    int v = (t < SCAN_BLKS) ? g_bsum[t] : 0;
    sa[t] = v;
    __syncthreads();
    int* pin = sa; int* pout = sb;
    #pragma unroll
    for (int o = 1; o < 512; o <<= 1) {
        pout[t] = pin[t] + ((t >= o) ? pin[t - o] : 0);
        __syncthreads();
        int* tmp = pin; pin = pout; pout = tmp;
    }
    g_bbase[t] = pin[t] - v;   // exclusive
}

__global__ void k_scanC() {
    __shared__ int sa[256], sb[256];
    int t = threadIdx.x;
    int i = blockIdx.x * 256 + t;
    int v = (i < SEGS) ? g_cnt[i] : 0;
    sa[t] = v;
    __syncthreads();
    int* pin = sa; int* pout = sb;
    #pragma unroll
    for (int o = 1; o < 256; o <<= 1) {
        pout[t] = pin[t] + ((t >= o) ? pin[t - o] : 0);
        __syncthreads();
        int* tmp = pin; pin = pout; pout = tmp;
    }
    if (i < SEGS) {
        int off = g_bbase[blockIdx.x] + pin[t] - v;
        g_off[i] = off;
        g_pos[i] = off;
    }
}

// ---------------- scatter: int4-vectorized, 4 edges per thread --------------
template <int G>
__device__ __forceinline__ void scatter_elem(int s, int d) {
    const int lo   = (G == 1) ? In : 0;
    const int hi   = (G == 0) ? Kn : (G == 1) ? Nn : In;
    const int base = (G == 0) ? 0 : (G == 1) ? Kn : 2 * Kn;
    if (d < lo || d >= hi) return;
    const float* ss = (G == 0) ? g_ssrc_dir : (G == 1) ? g_ssrc_ke : g_ssrc_ek;
    const float* sd = (G == 0) ? g_sdst_dir : (G == 1) ? g_sdst_ke : g_sdst_ek;
    float ev = expf(lrelu(__ldg(ss + s) + __ldg(sd + d)));
    int pos = atomicAdd(&g_pos[base + (d - lo)], 1);
    int u = (G == 0) ? s + In : s;                 // unified node id
    g_csr[pos] = make_int2(u, __float_as_int(ev));
}

template <int G>
__device__ __forceinline__ void scatter_quad(int q, const int4* __restrict__ src,
                                             const int4* __restrict__ dst) {
    int4 d = __ldg(dst + q);
    int4 s = __ldg(src + q);
    scatter_elem<G>(s.x, d.x);
    scatter_elem<G>(s.y, d.y);
    scatter_elem<G>(s.z, d.z);
    scatter_elem<G>(s.w, d.w);
}

__global__ void k_scatter(const int4* __restrict__ s0, const int4* __restrict__ d0,
                          const int4* __restrict__ s1, const int4* __restrict__ d1,
                          const int4* __restrict__ s2, const int4* __restrict__ d2) {
    int q = blockIdx.x * blockDim.x + threadIdx.x;
    const int Q1 = E1n / 4, Q2 = (E1n + E2n) / 4, QT = ETOT / 4;
    if (q >= QT) return;
    if (q < Q1)      scatter_quad<0>(q, s0, d0);
    else if (q < Q2) scatter_quad<1>(q - Q1, s1, d1);
    else             scatter_quad<2>(q - Q2, s2, d2);
}

// ---------------- single-pass softmax + aggregation: warp per segment --------
__global__ void __launch_bounds__(256) k_seg(const float4* __restrict__ exer,
                                             const float4* __restrict__ kn) {
    int w = (blockIdx.x * blockDim.x + threadIdx.x) >> 5;
    if (w >= SEGS) return;
    int lane = threadIdx.x & 31;
    int start = g_off[w];
    int end   = start + g_cnt[w];

    float4 acc = make_float4(0.f, 0.f, 0.f, 0.f);
    float den = 0.f;
    int e = start;
    for (; e + 4 <= end; e += 4) {
        int2 c0 = __ldg(g_csr + e);
        int2 c1 = __ldg(g_csr + e + 1);
        int2 c2 = __ldg(g_csr + e + 2);
        int2 c3 = __ldg(g_csr + e + 3);
        const float4* p0 = (c0.x < In) ? exer + (size_t)c0.x * 32 : kn + (size_t)(c0.x - In) * 32;
        const float4* p1 = (c1.x < In) ? exer + (size_t)c1.x * 32 : kn + (size_t)(c1.x - In) * 32;
        const float4* p2 = (c2.x < In) ? exer + (size_t)c2.x * 32 : kn + (size_t)(c2.x - In) * 32;
        const float4* p3 = (c3.x < In) ? exer + (size_t)c3.x * 32 : kn + (size_t)(c3.x - In) * 32;
        float4 v0 = __ldg(p0 + lane);
        float4 v1 = __ldg(p1 + lane);
        float4 v2 = __ldg(p2 + lane);
        float4 v3 = __ldg(p3 + lane);
        float e0 = __int_as_float(c0.y), e1 = __int_as_float(c1.y);
        float e2f = __int_as_float(c2.y), e3 = __int_as_float(c3.y);
        den += (e0 + e1) + (e2f + e3);
        acc.x = fmaf(e0, v0.x, acc.x); acc.y = fmaf(e0, v0.y, acc.y);
        acc.z = fmaf(e0, v0.z, acc.z); acc.w = fmaf(e0, v0.w, acc.w);
        acc.x = fmaf(e1, v1.x, acc.x); acc.y = fmaf(e1, v1.y, acc.y);
        acc.z = fmaf(e1, v1.z, acc.z); acc.w = fmaf(e1, v1.w, acc.w);
        acc.x = fmaf(e2f, v2.x, acc.x); acc.y = fmaf(e2f, v2.y, acc.y);
        acc.z = fmaf(e2f, v2.z, acc.z); acc.w = fmaf(e2f, v2.w, acc.w);
        acc.x = fmaf(e3, v3.x, acc.x); acc.y = fmaf(e3, v3.y, acc.y);
        acc.z = fmaf(e3, v3.z, acc.z); acc.w = fmaf(e3, v3.w, acc.w);
    }
    for (; e < end; e++) {
        int2 c0 = __ldg(g_csr + e);
        const float4* p0 = (c0.x < In) ? exer + (size_t)c0.x * 32 : kn + (size_t)(c0.x - In) * 32;
        float4 v0 = __ldg(p0 + lane);
        float e0 = __int_as_float(c0.y);
        den += e0;
        acc.x = fmaf(e0, v0.x, acc.x); acc.y = fmaf(e0, v0.y, acc.y);
        acc.z = fmaf(e0, v0.z, acc.z); acc.w = fmaf(e0, v0.w, acc.w);
    }
    float inv = (den > 0.f) ? 1.0f / den : 0.f;
    acc.x *= inv; acc.y *= inv; acc.z *= inv; acc.w *= inv;

    float* orow;
    if (w < Kn)            orow = g_agg_dir + (size_t)w * Dn;
    else if (w < 2 * Kn)   orow = g_agg_ke  + (size_t)(w - Kn) * Dn;
    else                   orow = g_agg_ek  + (size_t)(w - 2 * Kn) * Dn;
    ((float4*)orow)[lane] = acc;
}

// ---------------- fused row GEMM (+ rel head for A/B) via fma.rn.f32x2 --------
#define GEMM_BLKS_K ((Kn + 31) / 32)   // 625
#define GEMM_BLKS_I ((In + 31) / 32)   // 1563
#define GEMM_BLKS_TOT (2 * GEMM_BLKS_K + GEMM_BLKS_I)

__global__ void __launch_bounds__(128) k_gemm(const float* __restrict__ Wd,
                                              const float* __restrict__ Wke,
                                              const float* __restrict__ Wek,
                                              const float* __restrict__ relW1,
                                              const float* __restrict__ relb1,
                                              const float* __restrict__ relw2,
                                              float* __restrict__ exer_out) {
    int blk = blockIdx.x;
    const float* agg; const float* W; float* of; int rows; int row0;
    bool do_rel = (blk < 2 * GEMM_BLKS_K);
    if (blk < GEMM_BLKS_K) {
        agg = g_agg_dir; W = Wd;  of = g_A;      rows = Kn; row0 = blk * 32;
    } else if (blk < 2 * GEMM_BLKS_K) {
        agg = g_agg_ke;  W = Wke; of = g_B;      rows = Kn; row0 = (blk - GEMM_BLKS_K) * 32;
    } else {
        agg = g_agg_ek;  W = Wek; of = exer_out; rows = In; row0 = (blk - 2 * GEMM_BLKS_K) * 32;
    }
    __shared__ __align__(16) float shA[32][Dn];
    int t = threadIdx.x;
    const float4* agg4 = (const float4*)agg;
    for (int i = t; i < 1024; i += 128) {
        int r = i >> 5, c4 = i & 31;
        float4 v = (row0 + r < rows) ? __ldg(agg4 + (size_t)(row0 + r) * 32 + c4)
                                     : make_float4(0.f, 0.f, 0.f, 0.f);
        *(float4*)&shA[r][c4 * 4] = v;
    }
    __syncthreads();
    int cg = t & 31, rs = t >> 5;
    const float4* W4 = (const float4*)W;
    u64 acc2[8][4];
    #pragma unroll
    for (int r = 0; r < 8; r++)
        #pragma unroll
        for (int c = 0; c < 4; c++) acc2[r][c] = 0ull;
    #pragma unroll 4
    for (int k = 0; k < Dn; k += 2) {
        float4 wa = __ldg(W4 + k * 32 + cg);
        float4 wb = __ldg(W4 + (k + 1) * 32 + cg);
        u64 wx = pack2(wa.x, wb.x), wy = pack2(wa.y, wb.y);
        u64 wz = pack2(wa.z, wb.z), ww = pack2(wa.w, wb.w);
        #pragma unroll
        for (int r = 0; r < 8; r++) {
            u64 a2 = *(const u64*)&shA[rs * 8 + r][k];
            acc2[r][0] = ffma2(a2, wx, acc2[r][0]);
            acc2[r][1] = ffma2(a2, wy, acc2[r][1]);
            acc2[r][2] = ffma2(a2, wz, acc2[r][2]);
            acc2[r][3] = ffma2(a2, ww, acc2[r][3]);
        }
    }
    // finalize output tile
    float4 outv[8];
    #pragma unroll
    for (int r = 0; r < 8; r++)
        outv[r] = make_float4(hsum2(acc2[r][0]), hsum2(acc2[r][1]),
                              hsum2(acc2[r][2]), hsum2(acc2[r][3]));
    float4* out4 = (float4*)of;
    #pragma unroll
    for (int r = 0; r < 8; r++) {
        int row = row0 + rs * 8 + r;
        if (row < rows) out4[(size_t)row * 32 + cg] = outv[r];
    }
    if (!do_rel) return;

    // ---- fused rel head: s[row] = sum_c tanh((OUT @ relW1)[row][c] + b1[c]) * w2[c]
    __syncthreads();                       // everyone done reading old shA
    #pragma unroll
    for (int r = 0; r < 8; r++)
        *(float4*)&shA[rs * 8 + r][cg * 4] = outv[r];
    __syncthreads();

    const float4* R4 = (const float4*)relW1;
    #pragma unroll
    for (int r = 0; r < 8; r++)
        #pragma unroll
        for (int c = 0; c < 4; c++) acc2[r][c] = 0ull;
    #pragma unroll 4
    for (int k = 0; k < Dn; k += 2) {
        float4 wa = __ldg(R4 + k * 32 + cg);
        float4 wb = __ldg(R4 + (k + 1) * 32 + cg);
        u64 wx = pack2(wa.x, wb.x), wy = pack2(wa.y, wb.y);
        u64 wz = pack2(wa.z, wb.z), ww = pack2(wa.w, wb.w);
        #pragma unroll
        for (int r = 0; r < 8; r++) {
            u64 a2 = *(const u64*)&shA[rs * 8 + r][k];
            acc2[r][0] = ffma2(a2, wx, acc2[r][0]);
            acc2[r][1] = ffma2(a2, wy, acc2[r][1]);
            acc2[r][2] = ffma2(a2, wz, acc2[r][2]);
            acc2[r][3] = ffma2(a2, ww, acc2[r][3]);
        }
    }
    float4 bb = __ldg(((const float4*)relb1) + cg);
    float4 ww2 = __ldg(((const float4*)relw2) + cg);
    float part[8];
    #pragma unroll
    for (int r = 0; r < 8; r++) {
        part[r] = tanhf(hsum2(acc2[r][0]) + bb.x) * ww2.x
                + tanhf(hsum2(acc2[r][1]) + bb.y) * ww2.y
                + tanhf(hsum2(acc2[r][2]) + bb.z) * ww2.z
                + tanhf(hsum2(acc2[r][3]) + bb.w) * ww2.w;
    }
    #pragma unroll
    for (int o = 16; o; o >>= 1) {
        #pragma unroll
        for (int r = 0; r < 8; r++)
            part[r] += __shfl_xor_sync(0xffffffffu, part[r], o);
    }
    if (cg == 0) {
        float* sout = (blk < GEMM_BLKS_K) ? g_s1 : g_s2;
        #pragma unroll
        for (int r = 0; r < 8; r++) {
            int row = row0 + rs * 8 + r;
            if (row < Kn) sout[row] = part[r];
        }
    }
}

// kn_out = softmax([s1,s2]) gated mix of A and B
__global__ void k_combine(float4* __restrict__ out) {
    int i = blockIdx.x * blockDim.x + threadIdx.x;
    if (i >= Kn * 32) return;
    int row = i >> 5;
    float s1 = g_s1[row], s2 = g_s2[row];
    float mx = fmaxf(s1, s2);
    float e1 = expf(s1 - mx), e2 = expf(s2 - mx);
    float inv = 1.0f / (e1 + e2);
    float w1 = e1 * inv, w2 = e2 * inv;
    float4 a = ((const float4*)g_A)[i];
    float4 b = ((const float4*)g_B)[i];
    out[i] = make_float4(w1 * a.x + w2 * b.x, w1 * a.y + w2 * b.y,
                         w1 * a.z + w2 * b.z, w1 * a.w + w2 * b.w);
}

// ---------------- launch ----------------
extern "C" void kernel_launch(void* const* d_in, const int* in_sizes, int n_in,
                              void* d_out, int out_size) {
    (void)in_sizes; (void)n_in; (void)out_size;
    const float* kn    = (const float*)d_in[0];
    const float* exer  = (const float*)d_in[1];
    const float* Wd    = (const float*)d_in[2];
    const float* ad    = (const float*)d_in[3];
    const float* Wke   = (const float*)d_in[4];
    const float* ake   = (const float*)d_in[5];
    const float* Wek   = (const float*)d_in[6];
    const float* aek   = (const float*)d_in[7];
    const float* relW1 = (const float*)d_in[8];
    const float* relb1 = (const float*)d_in[9];
    const float* relw2 = (const float*)d_in[10];
    const int* dsrc  = (const int*)d_in[11];
    const int* ddst  = (const int*)d_in[12];
    const int* kesrc = (const int*)d_in[13];
    const int* kedst = (const int*)d_in[14];
    const int* eksrc = (const int*)d_in[15];
    const int* ekdst = (const int*)d_in[16];
    float* out = (float*)d_out;

    const float4* kn4   = (const float4*)kn;
    const float4* exer4 = (const float4*)exer;

    k_prep0<<<6 + ZERO_BLKS, 128>>>(Wd, ad, Wke, ake, Wek, aek);
    k_scal_count<<<SCAL_BLKS + CNT_BLKS, 256>>>(exer4, kn4,
                                                (const int4*)ddst, (const int4*)kedst,
                                                (const int4*)ekdst);
    k_scanA<<<SCAN_BLKS, 256>>>();
    k_scanB<<<1, 512>>>();
    k_scanC<<<SCAN_BLKS, 256>>>();
    k_scatter<<<(ETOT / 4 + 255) / 256, 256>>>((const int4*)dsrc, (const int4*)ddst,
                                               (const int4*)kesrc, (const int4*)kedst,
                                               (const int4*)eksrc, (const int4*)ekdst);
    k_seg<<<(SEGS * 32 + 255) / 256, 256>>>(exer4, kn4);
    k_gemm<<<GEMM_BLKS_TOT, 128>>>(Wd, Wke, Wek, relW1, relb1, relw2,
                                   out + (size_t)Kn * Dn);
    k_combine<<<(Kn * 32 + 255) / 256, 256>>>((float4*)out);
}